// round 7
// baseline (speedup 1.0000x reference)
#include <cuda_runtime.h>
#include <cuda_bf16.h>

// StrokeField, spatially binned (32^3 grid over contracted space).
// Strokes with d >= r+0.1 have t=0 exactly => skipping them is exact.
// Per-cell stroke lists are built in ascending stroke order => scan order kept.

#define N_POINTS  2097152
#define N_STROKES 500
#define NC        32
#define NCELLS    (NC*NC*NC)          // 32768
#define MAXL      N_STROKES
#define NTHREADS  256
#define K5_PPT    2                    // points per thread in blend
#define NB5       (N_POINTS/(NTHREADS*K5_PPT))   // 4096

// ---------------- scratch (device globals: allocation-free) ----------------
__device__ int    g_cellid[N_POINTS];        // cell per original point
__device__ int    g_hist[NCELLS];
__device__ int    g_cursor[NCELLS];          // scatter cursors (start offsets)
__device__ int    g_orig[N_POINTS];          // sorted pos -> original index
__device__ int    g_listCount[NCELLS];
__device__ int    g_list[NCELLS * MAXL];     // per-cell stroke ids (ascending)
__device__ float4 g_scG[N_STROKES];          // (-2cx,-2cy,-2cz,|c|^2)
__device__ float4 g_scH[N_STROKES];          // (5r+0.5, density, colR, colG)
__device__ float  g_scB[N_STROKES];          // colB

__device__ __forceinline__ float sqrt_approx(float x) {
    float r; asm("sqrt.approx.ftz.f32 %0, %1;" : "=f"(r) : "f"(x)); return r;
}
__device__ __forceinline__ float rcp_approx(float x) {
    float r; asm("rcp.approx.ftz.f32 %0, %1;" : "=f"(r) : "f"(x)); return r;
}
__device__ __forceinline__ int cell_of(float cx, float cy, float cz) {
    int ix = min(max((int)((cx + 1.f) * (NC * 0.5f)), 0), NC - 1);
    int iy = min(max((int)((cy + 1.f) * (NC * 0.5f)), 0), NC - 1);
    int iz = min(max((int)((cz + 1.f) * (NC * 0.5f)), 0), NC - 1);
    return (ix * NC + iy) * NC + iz;
}

// ---------------- K0: zero histogram ----------------
__global__ void k0_zero() {
    int i = blockIdx.x * blockDim.x + threadIdx.x;
    if (i < NCELLS) g_hist[i] = 0;
}

// ---------------- K1: contract, write warped coords, histogram ----------------
// 4 points/thread via float4 loads/stores (12 floats = 4 points).
__global__ __launch_bounds__(NTHREADS) void k1_warp_bin(
    const float4* __restrict__ coords4, float* __restrict__ out)
{
    int t = blockIdx.x * NTHREADS + threadIdx.x;
    float4 A = __ldg(&coords4[3*t+0]);
    float4 B = __ldg(&coords4[3*t+1]);
    float4 C = __ldg(&coords4[3*t+2]);
    float xs[4] = {A.x, A.w, B.z, C.y};
    float ys[4] = {A.y, B.x, B.w, C.z};
    float zs[4] = {A.z, B.y, C.x, C.w};
    float cx[4], cy[4], cz[4];
    int p0 = t * 4;
    #pragma unroll
    for (int j = 0; j < 4; j++) {
        float x = xs[j], y = ys[j], z = zs[j];
        float r2 = fmaf(x, x, fmaf(y, y, z*z));
        float n  = fmaxf(sqrt_approx(r2), 1e-9f);
        float iv = rcp_approx(n);
        float sc = (n <= 1.f) ? 0.5f : (2.f - iv) * iv * 0.5f;  // contract, /2
        cx[j] = x * sc; cy[j] = y * sc; cz[j] = z * sc;
        int cell = cell_of(cx[j], cy[j], cz[j]);
        g_cellid[p0 + j] = cell;
        atomicAdd(&g_hist[cell], 1);
    }
    float4* wout = (float4*)(out + 4*N_POINTS);
    wout[3*t+0] = make_float4(cx[0], cy[0], cz[0], cx[1]);
    wout[3*t+1] = make_float4(cy[1], cz[1], cx[2], cy[2]);
    wout[3*t+2] = make_float4(cz[2], cx[3], cy[3], cz[3]);
}

// ---------------- K2: exclusive scan (32768 bins) + stroke constants ----------------
__global__ __launch_bounds__(1024) void k2_scan_const(
    const float* __restrict__ shape, const float* __restrict__ color,
    const float* __restrict__ alpha)
{
    __shared__ int partial[1024];
    int t = threadIdx.x;
    int base = t * (NCELLS / 1024);   // 32 bins each
    int loc[32]; int sum = 0;
    #pragma unroll
    for (int i = 0; i < 32; i++) { loc[i] = sum; sum += g_hist[base + i]; }
    partial[t] = sum;
    __syncthreads();
    for (int off = 1; off < 1024; off <<= 1) {
        int v = (t >= off) ? partial[t - off] : 0;
        __syncthreads();
        partial[t] += v;
        __syncthreads();
    }
    int offset = (t > 0) ? partial[t - 1] : 0;
    #pragma unroll
    for (int i = 0; i < 32; i++) g_cursor[base + i] = offset + loc[i];

    if (t < N_STROKES) {
        float cx = shape[4*t+0], cy = shape[4*t+1], cz = shape[4*t+2], r = shape[4*t+3];
        g_scG[t] = make_float4(-2.f*cx, -2.f*cy, -2.f*cz,
                               fmaf(cx,cx, fmaf(cy,cy, cz*cz)));
        float dp = fmaxf(alpha[t], 0.f) * 50.f;
        g_scH[t] = make_float4(fmaf(5.f, r, 0.5f), dp, color[3*t+0], color[3*t+1]);
        g_scB[t] = color[3*t+2];
    }
}

// ---------------- K3: counting-sort scatter (index only, 4 pts/thread) ----------------
__global__ __launch_bounds__(NTHREADS) void k3_scatter()
{
    int t = blockIdx.x * NTHREADS + threadIdx.x;
    int4 c = *(const int4*)&g_cellid[t * 4];
    int p = t * 4;
    int pos0 = atomicAdd(&g_cursor[c.x], 1);
    int pos1 = atomicAdd(&g_cursor[c.y], 1);
    int pos2 = atomicAdd(&g_cursor[c.z], 1);
    int pos3 = atomicAdd(&g_cursor[c.w], 1);
    g_orig[pos0] = p;
    g_orig[pos1] = p + 1;
    g_orig[pos2] = p + 2;
    g_orig[pos3] = p + 3;
}

// ---------------- K4: per-cell stroke lists (warp/cell, ballot compaction) ----------------
__global__ __launch_bounds__(NTHREADS) void k4_lists(const float* __restrict__ shape)
{
    int warp = (blockIdx.x * NTHREADS + threadIdx.x) >> 5;
    int lane = threadIdx.x & 31;
    if (warp >= NCELLS) return;
    int iz = warp % NC, iy = (warp / NC) % NC, ix = warp / (NC * NC);
    const float w = 2.f / NC;
    float lox = -1.f + ix * w, hix = lox + w;
    float loy = -1.f + iy * w, hiy = loy + w;
    float loz = -1.f + iz * w, hiz = loz + w;
    int count = 0;
    for (int s0 = 0; s0 < N_STROKES; s0 += 32) {
        int s = s0 + lane;
        bool pred = false;
        if (s < N_STROKES) {
            float cx = shape[4*s+0], cy = shape[4*s+1], cz = shape[4*s+2], r = shape[4*s+3];
            float dx = fmaxf(fmaxf(lox - cx, cx - hix), 0.f);
            float dy = fmaxf(fmaxf(loy - cy, cy - hiy), 0.f);
            float dz = fmaxf(fmaxf(loz - cz, cz - hiz), 0.f);
            float d2 = fmaf(dx, dx, fmaf(dy, dy, dz*dz));
            float rr = r + 0.101f;           // band r+0.1 + margin for approx sqrt
            pred = d2 < rr * rr;
        }
        unsigned m = __ballot_sync(0xffffffffu, pred);
        if (pred) {
            int off = count + __popc(m & ((1u << lane) - 1u));
            g_list[warp * MAXL + off] = s;
        }
        count += __popc(m);
    }
    if (lane == 0) g_listCount[warp] = count;
}

// ---------------- K5: blend ----------------
struct Acc { float d, r, g, b, w; };

__device__ __forceinline__ void blend_one(
    Acc& a, float px, float py, float pz, float pp, int s)
{
    float4 G = __ldg(&g_scG[s]);
    float4 H = __ldg(&g_scH[s]);
    float cb = __ldg(&g_scB[s]);
    float d2 = fmaf(px, G.x, fmaf(py, G.y, fmaf(pz, G.z, pp + G.w)));
    float d  = sqrt_approx(fabsf(d2));
    float t  = __saturatef(fmaf(d, -5.f, H.x));
    float u  = 1.f - t;
    a.d = fmaf(u, a.d, t * H.y);
    a.r = fmaf(u, a.r, t * H.z);
    a.g = fmaf(u, a.g, t * H.w);
    a.b = fmaf(u, a.b, t * cb);
    a.w *= u;
}

__device__ __forceinline__ void write_out(
    float* __restrict__ out, int p, const Acc& a)
{
    float invd = 1.f / (1.000001f - a.w);
    out[p] = a.d;
    out[N_POINTS + 3*p + 0] = __saturatef(a.r * invd);
    out[N_POINTS + 3*p + 1] = __saturatef(a.g * invd);
    out[N_POINTS + 3*p + 2] = __saturatef(a.b * invd);
}

__global__ __launch_bounds__(NTHREADS) void k5_blend(float* __restrict__ out)
{
    int t  = blockIdx.x * NTHREADS + threadIdx.x;
    int2 o = *(const int2*)&g_orig[t * 2];

    const float* wc = out + 4*N_POINTS;
    float x0 = __ldg(&wc[3*o.x+0]), y0 = __ldg(&wc[3*o.x+1]), z0 = __ldg(&wc[3*o.x+2]);
    float x1 = __ldg(&wc[3*o.y+0]), y1 = __ldg(&wc[3*o.y+1]), z1 = __ldg(&wc[3*o.y+2]);
    float pp0 = fmaf(x0, x0, fmaf(y0, y0, z0*z0));
    float pp1 = fmaf(x1, x1, fmaf(y1, y1, z1*z1));
    int c0 = cell_of(x0, y0, z0);
    int c1 = cell_of(x1, y1, z1);

    Acc a0 = {0.f, 0.f, 0.f, 0.f, 1.f};
    Acc a1 = {0.f, 0.f, 0.f, 0.f, 1.f};

    if (c0 == c1) {
        // common case: both points in same cell -> dual-point loop (2x ILP)
        int nl = g_listCount[c0];
        const int* L = &g_list[c0 * MAXL];
        for (int i = 0; i < nl; i++) {
            int s = __ldg(&L[i]);
            float4 G = __ldg(&g_scG[s]);
            float4 H = __ldg(&g_scH[s]);
            float cb = __ldg(&g_scB[s]);
            float d20 = fmaf(x0, G.x, fmaf(y0, G.y, fmaf(z0, G.z, pp0 + G.w)));
            float d21 = fmaf(x1, G.x, fmaf(y1, G.y, fmaf(z1, G.z, pp1 + G.w)));
            float d0 = sqrt_approx(fabsf(d20));
            float d1 = sqrt_approx(fabsf(d21));
            float t0 = __saturatef(fmaf(d0, -5.f, H.x));
            float t1 = __saturatef(fmaf(d1, -5.f, H.x));
            float u0 = 1.f - t0, u1 = 1.f - t1;
            a0.d = fmaf(u0, a0.d, t0 * H.y);  a1.d = fmaf(u1, a1.d, t1 * H.y);
            a0.r = fmaf(u0, a0.r, t0 * H.z);  a1.r = fmaf(u1, a1.r, t1 * H.z);
            a0.g = fmaf(u0, a0.g, t0 * H.w);  a1.g = fmaf(u1, a1.g, t1 * H.w);
            a0.b = fmaf(u0, a0.b, t0 * cb);   a1.b = fmaf(u1, a1.b, t1 * cb);
            a0.w *= u0;                       a1.w *= u1;
        }
    } else {
        int nl0 = g_listCount[c0];
        const int* L0 = &g_list[c0 * MAXL];
        for (int i = 0; i < nl0; i++) blend_one(a0, x0, y0, z0, pp0, __ldg(&L0[i]));
        int nl1 = g_listCount[c1];
        const int* L1 = &g_list[c1 * MAXL];
        for (int i = 0; i < nl1; i++) blend_one(a1, x1, y1, z1, pp1, __ldg(&L1[i]));
    }

    write_out(out, o.x, a0);
    write_out(out, o.y, a1);
}

// ---------------- launch ----------------
extern "C" void kernel_launch(void* const* d_in, const int* in_sizes, int n_in,
                              void* d_out, int out_size) {
    const float* coords = (const float*)d_in[0];
    const float* shape  = (const float*)d_in[1];
    const float* color  = (const float*)d_in[2];
    const float* alpha  = (const float*)d_in[3];
    float* out = (float*)d_out;

    k0_zero<<<NCELLS / 256, 256>>>();
    k1_warp_bin<<<N_POINTS / (NTHREADS * 4), NTHREADS>>>((const float4*)coords, out);
    k2_scan_const<<<1, 1024>>>(shape, color, alpha);
    k4_lists<<<(NCELLS * 32) / NTHREADS, NTHREADS>>>(shape);  // independent of scan
    k3_scatter<<<N_POINTS / (NTHREADS * 4), NTHREADS>>>();
    k5_blend<<<NB5, NTHREADS>>>(out);
}